// round 5
// baseline (speedup 1.0000x reference)
#include <cuda_runtime.h>
#include <cuda_bf16.h>

// Problem constants (fixed shapes from setup_inputs)
constexpr int B    = 4;
constexpr int S    = 2048;
constexpr int N    = B * S;        // 8192
constexpr int KNEG = 4;
constexpr int NK   = N * KNEG;     // 32768
constexpr int WMAX = 16;

#define SOFT 1e-6f
#define EPSF 1e-9f
#define CUT2 0.01f

constexpr int FB    = 256;           // force blocks (S/32 * B)
constexpr int LB    = 64;            // loss partial blocks
constexpr int TOTAL = FB + LB;       // 320
constexpr int TPB   = 512;           // 16 warps
constexpr int FNW   = TPB / 32;
constexpr int JPW   = S / FNW;       // 128 j per warp

__device__ __align__(16) float g_lpart[LB * 8];
__device__ unsigned int g_cnt;       // zero-init; reset by final block each run

// ---------------- raw approx MUFU --------------------------------------
__device__ __forceinline__ float rsq(float x) {
    float r; asm("rsqrt.approx.f32 %0, %1;" : "=f"(r) : "f"(x)); return r;
}
__device__ __forceinline__ float rcp(float x) {
    float r; asm("rcp.approx.f32 %0, %1;" : "=f"(r) : "f"(x)); return r;
}

// ---------------------------------------------------------------------------
__device__ __forceinline__ float mind2_row(const float4 a, const float4 b4,
                                           const float* __restrict__ wsh, int W)
{
    float best = 3.4e38f;
    for (int w = 0; w < W; w++) {
        const float* wc = &wsh[w * 8];
        float d = 0.0f, t;
        t = a.x  - wc[0]; d = fmaf(t, t, d);
        t = a.y  - wc[1]; d = fmaf(t, t, d);
        t = a.z  - wc[2]; d = fmaf(t, t, d);
        t = a.w  - wc[3]; d = fmaf(t, t, d);
        t = b4.x - wc[4]; d = fmaf(t, t, d);
        t = b4.y - wc[5]; d = fmaf(t, t, d);
        t = b4.z - wc[6]; d = fmaf(t, t, d);
        t = b4.w - wc[7]; d = fmaf(t, t, d);
        best = fminf(best, d);
    }
    return best;   // min(dist)^2 == min(dist^2)
}

// ---------------------------------------------------------------------------
// Fused kernel. Blocks [0,FB): force tiles. Blocks [FB,TOTAL): loss partials.
// Last-arriving block (threadfence + atomic ticket) folds the loss final.
// Entropy term cancels in F_pos - F_neg and is never computed.
// ---------------------------------------------------------------------------
__global__ __launch_bounds__(TPB)
void fused_kernel(const float* __restrict__ pos,
                  const float* __restrict__ mass,
                  const float* __restrict__ vel,
                  const float* __restrict__ pos8,
                  const float* __restrict__ pp2d,
                  const float* __restrict__ pp8,
                  const float* __restrict__ pmass,
                  const float* __restrict__ np2d,
                  const float* __restrict__ np8,
                  const float* __restrict__ nmass,
                  const float* __restrict__ emass,
                  const float* __restrict__ wells,
                  const float* __restrict__ G_,
                  const float* __restrict__ rep_,
                  const float* __restrict__ ws_,
                  int W,
                  float* __restrict__ out)
{
    __shared__ __align__(16) float4 tile[S];   // 32 KB (x, y, mass, pad)
    __shared__ float2 red[FNW][32];            // 4 KB
    __shared__ float wsh[WMAX * 8];
    __shared__ float lred[FNW][8];
    __shared__ unsigned s_last;

    const int tid  = threadIdx.x;
    const int lane = tid & 31;
    const int warp = tid >> 5;
    const float Gp = fmaxf(G_[0], 0.0f);

    if (blockIdx.x < FB) {
        // =================== FORCE TILE ===================
        const int b  = blockIdx.x >> 6;
        const int i0 = (blockIdx.x & 63) * 32;

        const float reps = fmaxf(rep_[0], 0.0f);
        const float c1   = -10.0f * reps;   // reps*relu(1-d/0.1) = max(c1*d+c0,0)
        const float c0   = reps;

        for (int j = tid; j < S; j += TPB) {
            float2 p = ((const float2*)pos)[b * S + j];
            tile[j] = make_float4(p.x, p.y, mass[b * S + j], 0.0f);
        }
        __syncthreads();

        const float pix = tile[i0 + lane].x;
        const float piy = tile[i0 + lane].y;
        const float ngm = -Gp * tile[i0 + lane].z;

        const float4* tl = tile + warp * JPW;

        float fx0 = 0.f, fy0 = 0.f, fx1 = 0.f, fy1 = 0.f;

#pragma unroll 4
        for (int h = 0; h < JPW; h += 2) {
            const float4 t0 = tl[h];
            const float4 t1 = tl[h + 1];
            const float dx0 = t0.x - pix, dy0 = t0.y - piy;
            const float dx1 = t1.x - pix, dy1 = t1.y - piy;
            const float d20 = fmaf(dx0, dx0, fmaf(dy0, dy0, SOFT));
            const float d21 = fmaf(dx1, dx1, fmaf(dy1, dy1, SOFT));
            const float u0 = rsq(d20);
            const float u1 = rsq(d21);
            float w0 = (ngm * t0.z) * (u0 * u0) * u0;   // -att/dist
            float w1 = (ngm * t1.z) * (u1 * u1) * u1;
            if (__any_sync(0xffffffffu, fminf(d20, d21) < CUT2)) {
                const float d0 = d20 * u0;
                const float tt0 = fmaxf(fmaf(d0, c1, c0), 0.0f);
                w0 = fmaf(tt0 * rcp(fmaf(d20, d0, EPSF)), u0, w0);
                const float d1 = d21 * u1;
                const float tt1 = fmaxf(fmaf(d1, c1, c0), 0.0f);
                w1 = fmaf(tt1 * rcp(fmaf(d21, d1, EPSF)), u1, w1);
            }
            fx0 = fmaf(w0, dx0, fx0);
            fy0 = fmaf(w0, dy0, fy0);
            fx1 = fmaf(w1, dx1, fx1);
            fy1 = fmaf(w1, dy1, fy1);
        }

        red[warp][lane] = make_float2(fx0 + fx1, fy0 + fy1);
        __syncthreads();

        if (warp == 0) {
            float sxs = 0.0f, sys = 0.0f;
#pragma unroll
            for (int w = 0; w < FNW; w++) {
                sxs += red[w][lane].x;
                sys += red[w][lane].y;
            }
            ((float2*)out)[b * S + i0 + lane] = make_float2(sxs, sys);
        }
    } else {
        // =================== LOSS PARTIAL ===================
        const int lb = blockIdx.x - FB;
        if (tid < W * 8) wsh[tid] = wells[tid];
        __syncthreads();

        float s1 = 0.f, s2 = 0.f, s3 = 0.f, s4 = 0.f, s5 = 0.f, s6 = 0.f, s7 = 0.f;
        const int stride = LB * TPB;          // 32768

        for (int i = lb * TPB + tid; i < N; i += stride) {
            float2 p = ((const float2*)pos)[i];
            float2 q = ((const float2*)pp2d)[i];
            float dx = p.x - q.x, dy = p.y - q.y;
            float d2 = fmaf(dx, dx, dy * dy);
            float m = mass[i];
            s1 = fmaf(m * pmass[i], rsq(d2), s1);   // eps vs dist: <=1e-6 rel
            s6 += m;
            float2 v = ((const float2*)vel)[i];
            s7 = fmaf(v.x, v.x, fmaf(v.y, v.y, s7));

            float4 a  = ((const float4*)pos8)[i * 2];
            float4 b4 = ((const float4*)pos8)[i * 2 + 1];
            s3 += mind2_row(a, b4, wsh, W);
            a  = ((const float4*)pp8)[i * 2];
            b4 = ((const float4*)pp8)[i * 2 + 1];
            s4 += mind2_row(a, b4, wsh, W);
        }

        for (int n = lb * TPB + tid; n < NK; n += stride) {
            float2 p = ((const float2*)pos)[n / KNEG];
            float2 q = ((const float2*)np2d)[n];
            float dx = p.x - q.x, dy = p.y - q.y;
            float d2 = fmaf(dx, dx, dy * dy);
            s2 = fmaf(emass[n] * nmass[n], rsq(d2), s2);

            float4 a  = ((const float4*)np8)[n * 2];
            float4 b4 = ((const float4*)np8)[n * 2 + 1];
            s5 += mind2_row(a, b4, wsh, W);
        }

        float vals[7] = {s1, s2, s3, s4, s5, s6, s7};
#pragma unroll
        for (int k = 0; k < 7; k++) {
#pragma unroll
            for (int off = 16; off > 0; off >>= 1)
                vals[k] += __shfl_down_sync(0xffffffffu, vals[k], off);
        }
        if (lane == 0) {
#pragma unroll
            for (int k = 0; k < 7; k++) lred[warp][k] = vals[k];
        }
        __syncthreads();
        if (warp == 0) {
#pragma unroll
            for (int k = 0; k < 7; k++) {
                float v = (lane < FNW) ? lred[lane][k] : 0.0f;
#pragma unroll
                for (int off = 8; off > 0; off >>= 1)
                    v += __shfl_down_sync(0xffffffffu, v, off);
                if (lane == 0) g_lpart[lb * 8 + k] = v;
            }
        }
    }

    // =================== TICKET + LOSS FINAL ===================
    __syncthreads();
    if (tid == 0) {
        __threadfence();
        unsigned t = atomicAdd(&g_cnt, 1u);
        s_last = (t == TOTAL - 1) ? 1u : 0u;
    }
    __syncthreads();
    if (s_last) {
        __threadfence();
        if (warp == 0) {
            float s[7];
#pragma unroll
            for (int k = 0; k < 7; k++) {
                float v = g_lpart[lane * 8 + k] + g_lpart[(lane + 32) * 8 + k];
#pragma unroll
                for (int off = 16; off > 0; off >>= 1)
                    v += __shfl_down_sync(0xffffffffu, v, off);
                s[k] = v;   // valid on lane 0
            }
            if (lane == 0) {
                const float ws = fmaxf(ws_[0], 0.0f);
                const float S1 = s[0], S2 = s[1], S3 = s[2], S4 = s[3],
                            S5 = s[4], S6 = s[5], S7 = s[6];
                const float U_pos = -Gp * (S1 / (float)N) +
                                    ws * (S3 + S4) / (2.0f * (float)N);
                const float U_neg = -Gp * (S2 / (float)NK) +
                                    ws * ((float)KNEG * S3 + S5) / (2.0f * (float)NK);
                const float fe = fmaxf(1.0f + U_pos - U_neg, 0.0f);
                const float ke = 1e-3f * 0.5f * (S6 / (float)N) * (S7 / (float)N);
                out[N * 2] = fe + ke;
                g_cnt = 0;   // reset for next graph replay
            }
        }
    }
}

// ---------------------------------------------------------------------------
extern "C" void kernel_launch(void* const* d_in, const int* in_sizes, int n_in,
                              void* d_out, int out_size)
{
    const float* positions_2d = (const float*)d_in[0];
    const float* masses       = (const float*)d_in[1];
    const float* vel_2d       = (const float*)d_in[2];
    const float* pos_8d       = (const float*)d_in[3];
    const float* pos_pos_2d   = (const float*)d_in[4];
    const float* pos_pos_8d   = (const float*)d_in[5];
    const float* positive_m   = (const float*)d_in[6];
    const float* neg_pos_2d   = (const float*)d_in[7];
    const float* neg_pos_8d   = (const float*)d_in[8];
    const float* neg_masses   = (const float*)d_in[9];
    const float* exp_masses   = (const float*)d_in[10];
    const float* G            = (const float*)d_in[11];
    const float* rep_strength = (const float*)d_in[12];
    const float* well_centers = (const float*)d_in[13];
    const float* well_str     = (const float*)d_in[14];
    // temperature (15) / entropy_coeff (16) unused: entropy cancels.

    const int W = in_sizes[13] / 8;
    float* out = (float*)d_out;

    fused_kernel<<<TOTAL, TPB>>>(positions_2d, masses, vel_2d, pos_8d,
                                 pos_pos_2d, pos_pos_8d, positive_m,
                                 neg_pos_2d, neg_pos_8d, neg_masses,
                                 exp_masses, well_centers,
                                 G, rep_strength, well_str, W, out);
}

// round 7
// speedup vs baseline: 1.0015x; 1.0015x over previous
#include <cuda_runtime.h>
#include <cuda_bf16.h>

// Problem constants (fixed shapes from setup_inputs)
constexpr int B    = 4;
constexpr int S    = 2048;
constexpr int N    = B * S;        // 8192
constexpr int KNEG = 4;
constexpr int NK   = N * KNEG;     // 32768
constexpr int WMAX = 16;

#define SOFT 1e-6f
#define EPSF 1e-9f
#define CUT2 0.01f

constexpr int FB    = 256;           // force blocks (S/32 * B)
constexpr int LB    = 40;            // loss partial blocks
constexpr int TOTAL = FB + LB;       // 296 = 2 * 148 SMs -> balanced wave
constexpr int TPB   = 512;           // 16 warps
constexpr int FNW   = TPB / 32;
constexpr int JPW   = S / FNW;       // 128 j per warp
constexpr int HPW   = JPW / 2;       // 64 packed iterations per warp

__device__ __align__(16) float g_lpart[LB * 8];
__device__ unsigned int g_cnt;       // zero-init; reset by final block each run

// ---------------- raw approx MUFU + f32x2 helpers ---------------------------
typedef unsigned long long u64;

__device__ __forceinline__ float rsq(float x) {
    float r; asm("rsqrt.approx.f32 %0, %1;" : "=f"(r) : "f"(x)); return r;
}
__device__ __forceinline__ float rcp(float x) {
    float r; asm("rcp.approx.f32 %0, %1;" : "=f"(r) : "f"(x)); return r;
}
__device__ __forceinline__ u64 pk(float lo, float hi) {
    u64 r; asm("mov.b64 %0, {%1, %2};" : "=l"(r) : "f"(lo), "f"(hi)); return r;
}
__device__ __forceinline__ void upk(float& lo, float& hi, u64 v) {
    asm("mov.b64 {%0, %1}, %2;" : "=f"(lo), "=f"(hi) : "l"(v));
}
__device__ __forceinline__ u64 add2(u64 a, u64 b) {
    u64 d; asm("add.rn.f32x2 %0, %1, %2;" : "=l"(d) : "l"(a), "l"(b)); return d;
}
__device__ __forceinline__ u64 mul2(u64 a, u64 b) {
    u64 d; asm("mul.rn.f32x2 %0, %1, %2;" : "=l"(d) : "l"(a), "l"(b)); return d;
}
__device__ __forceinline__ u64 fma2(u64 a, u64 b, u64 c) {
    u64 d; asm("fma.rn.f32x2 %0, %1, %2, %3;" : "=l"(d) : "l"(a), "l"(b), "l"(c)); return d;
}

// ---------------------------------------------------------------------------
__device__ __forceinline__ float mind2_row(const float4 a, const float4 b4,
                                           const float* __restrict__ wsh, int W)
{
    float best = 3.4e38f;
    for (int w = 0; w < W; w++) {
        const float* wc = &wsh[w * 8];
        float d = 0.0f, t;
        t = a.x  - wc[0]; d = fmaf(t, t, d);
        t = a.y  - wc[1]; d = fmaf(t, t, d);
        t = a.z  - wc[2]; d = fmaf(t, t, d);
        t = a.w  - wc[3]; d = fmaf(t, t, d);
        t = b4.x - wc[4]; d = fmaf(t, t, d);
        t = b4.y - wc[5]; d = fmaf(t, t, d);
        t = b4.z - wc[6]; d = fmaf(t, t, d);
        t = b4.w - wc[7]; d = fmaf(t, t, d);
        best = fminf(best, d);
    }
    return best;   // min(dist)^2 == min(dist^2)
}

// ---------------------------------------------------------------------------
// Fused kernel. Blocks [0,FB): force tiles. Gram-screened f32x2 fast path;
// exact diff-form path (attraction + repulsion) whenever any lane is inside
// the cutoff region — this includes every diagonal pair, whose contribution
// is then exactly 0 (mg * dx with dx == 0), matching the reference.
// Blocks [FB,TOTAL): loss partials. Last block (ticket) folds loss final.
// Entropy term cancels in F_pos - F_neg and is never computed.
// ---------------------------------------------------------------------------
__global__ __launch_bounds__(TPB)
void fused_kernel(const float* __restrict__ pos,
                  const float* __restrict__ mass,
                  const float* __restrict__ vel,
                  const float* __restrict__ pos8,
                  const float* __restrict__ pp2d,
                  const float* __restrict__ pp8,
                  const float* __restrict__ pmass,
                  const float* __restrict__ np2d,
                  const float* __restrict__ np8,
                  const float* __restrict__ nmass,
                  const float* __restrict__ emass,
                  const float* __restrict__ wells,
                  const float* __restrict__ G_,
                  const float* __restrict__ rep_,
                  const float* __restrict__ ws_,
                  int W,
                  float* __restrict__ out)
{
    // A[h]  = (x_{2h}, x_{2h+1}, y_{2h}, y_{2h+1})
    // Bm[h] = (G*m_{2h}, G*m_{2h+1}, r_{2h}, r_{2h+1}),  r_j = x_j^2 + y_j^2
    __shared__ __align__(16) float4 A[S / 2];    // 16 KB
    __shared__ __align__(16) float4 Bm[S / 2];   // 16 KB
    __shared__ float2 red[FNW][32];              // 4 KB
    __shared__ float wsh[WMAX * 8];
    __shared__ float lred[FNW][8];
    __shared__ unsigned s_last;

    const int tid  = threadIdx.x;
    const int lane = tid & 31;
    const int warp = tid >> 5;
    const float Gp = fmaxf(G_[0], 0.0f);

    if (blockIdx.x < FB) {
        // =================== FORCE TILE ===================
        const int b  = blockIdx.x >> 6;
        const int i0 = (blockIdx.x & 63) * 32;

        const float reps = fmaxf(rep_[0], 0.0f);
        const float c1   = -10.0f * reps;   // reps*relu(1-d/0.1) = max(c1*d+c0,0)
        const float c0   = reps;

        for (int h = tid; h < S / 2; h += TPB) {
            const float4 pp = ((const float4*)pos)[b * (S / 2) + h]; // x0,y0,x1,y1
            const float2 mm = ((const float2*)mass)[b * (S / 2) + h];
            A[h]  = make_float4(pp.x, pp.z, pp.y, pp.w);
            Bm[h] = make_float4(Gp * mm.x, Gp * mm.y,
                                fmaf(pp.x, pp.x, pp.y * pp.y),
                                fmaf(pp.z, pp.z, pp.w * pp.w));
        }
        __syncthreads();

        const int i = i0 + lane;
        const float2 pi = ((const float2*)pos)[b * S + i];
        const float  mi = mass[b * S + i];
        const float pix = pi.x, piy = pi.y;
        const float ri  = fmaf(pix, pix, fmaf(piy, piy, SOFT));
        const float ngmi = -Gp * mi;       // for exact-path attraction

        const u64 ax2 = pk(-2.0f * pix, -2.0f * pix);
        const u64 ay2 = pk(-2.0f * piy, -2.0f * piy);
        const u64 ri2 = pk(ri, ri);

        const float4* Aw = A  + warp * HPW;
        const float4* Bw = Bm + warp * HPW;

        u64 swx = 0ull, swy = 0ull, sw = 0ull;  // Gram-path accumulators
        float rx = 0.0f, ry = 0.0f;             // exact-path accumulators

#pragma unroll 4
        for (int h = 0; h < HPW; h++) {
            const float4 a  = Aw[h];   // x0,x1,y0,y1 (LDS.128 broadcast)
            const float4 bm = Bw[h];   // gm0,gm1,r0,r1
            const u64 xp  = pk(a.x, a.y);
            const u64 yp  = pk(a.z, a.w);
            const u64 rj  = pk(bm.z, bm.w);

            const u64 d2 = add2(fma2(ax2, xp, fma2(ay2, yp, rj)), ri2);
            float d2a, d2b; upk(d2a, d2b, d2);

            if (__any_sync(0xffffffffu, fminf(d2a, d2b) < CUT2)) {
                // exact diff-form for BOTH pairs (att + rep); no Gram pollution.
                // Diagonal: dx=dy=0 -> contribution exactly 0.
                const float dx0 = a.x - pix, dy0 = a.z - piy;
                const float e0  = fmaf(dx0, dx0, fmaf(dy0, dy0, SOFT));
                const float v0  = rsq(e0);
                const float de0 = e0 * v0;
                const float t0  = fmaxf(fmaf(de0, c1, c0), 0.0f);
                float mg0 = (ngmi * bm.x) * (v0 * v0) * v0;          // -att/dist (mi folded)
                mg0 = fmaf(t0 * rcp(fmaf(e0, de0, EPSF)), v0, mg0);  // + rep/dist
                rx = fmaf(mg0, dx0, rx);
                ry = fmaf(mg0, dy0, ry);

                const float dx1 = a.y - pix, dy1 = a.w - piy;
                const float e1  = fmaf(dx1, dx1, fmaf(dy1, dy1, SOFT));
                const float v1  = rsq(e1);
                const float de1 = e1 * v1;
                const float t1  = fmaxf(fmaf(de1, c1, c0), 0.0f);
                float mg1 = (ngmi * bm.y) * (v1 * v1) * v1;
                mg1 = fmaf(t1 * rcp(fmaf(e1, de1, EPSF)), v1, mg1);
                rx = fmaf(mg1, dx1, rx);
                ry = fmaf(mg1, dy1, ry);
            } else {
                // Gram fast path: d2 >= CUT2 - 1e-5 > 0 on all lanes.
                const float u0 = rsq(d2a);
                const float u1 = rsq(d2b);
                const u64 up = pk(u0, u1);
                const u64 gm2 = pk(bm.x, bm.y);
                const u64 u2 = mul2(up, up);
                const u64 u3 = mul2(u2, up);
                const u64 w  = mul2(gm2, u3);     // G*mj*u^3 (mi folded at end)
                swx = fma2(w, xp, swx);
                swy = fma2(w, yp, swy);
                sw  = add2(sw, w);
            }
        }

        float swxa, swxb, swya, swyb, swa, swb;
        upk(swxa, swxb, swx);
        upk(swya, swyb, swy);
        upk(swa,  swb,  sw);
        const float SWX = swxa + swxb;
        const float SWY = swya + swyb;
        const float SW  = swa + swb;
        // attraction via linearity: F_att = -mi * (SWX - pix*SW); + exact part
        const float fx = fmaf(-mi, fmaf(-pix, SW, SWX), rx);
        const float fy = fmaf(-mi, fmaf(-piy, SW, SWY), ry);

        red[warp][lane] = make_float2(fx, fy);
        __syncthreads();

        if (warp == 0) {
            float sxs = 0.0f, sys = 0.0f;
#pragma unroll
            for (int w = 0; w < FNW; w++) {
                sxs += red[w][lane].x;
                sys += red[w][lane].y;
            }
            ((float2*)out)[b * S + i0 + lane] = make_float2(sxs, sys);
        }
    } else {
        // =================== LOSS PARTIAL ===================
        const int lb = blockIdx.x - FB;
        if (tid < W * 8) wsh[tid] = wells[tid];
        __syncthreads();

        float s1 = 0.f, s2 = 0.f, s3 = 0.f, s4 = 0.f, s5 = 0.f, s6 = 0.f, s7 = 0.f;
        const int stride = LB * TPB;          // 20480

        for (int i = lb * TPB + tid; i < N; i += stride) {
            float2 p = ((const float2*)pos)[i];
            float2 q = ((const float2*)pp2d)[i];
            float dx = p.x - q.x, dy = p.y - q.y;
            float d2 = fmaf(dx, dx, dy * dy);
            float m = mass[i];
            s1 = fmaf(m * pmass[i], rsq(d2), s1);   // eps vs dist: <=1e-6 rel
            s6 += m;
            float2 v = ((const float2*)vel)[i];
            s7 = fmaf(v.x, v.x, fmaf(v.y, v.y, s7));

            float4 a  = ((const float4*)pos8)[i * 2];
            float4 b4 = ((const float4*)pos8)[i * 2 + 1];
            s3 += mind2_row(a, b4, wsh, W);
            a  = ((const float4*)pp8)[i * 2];
            b4 = ((const float4*)pp8)[i * 2 + 1];
            s4 += mind2_row(a, b4, wsh, W);
        }

        for (int n = lb * TPB + tid; n < NK; n += stride) {
            float2 p = ((const float2*)pos)[n / KNEG];
            float2 q = ((const float2*)np2d)[n];
            float dx = p.x - q.x, dy = p.y - q.y;
            float d2 = fmaf(dx, dx, dy * dy);
            s2 = fmaf(emass[n] * nmass[n], rsq(d2), s2);

            float4 a  = ((const float4*)np8)[n * 2];
            float4 b4 = ((const float4*)np8)[n * 2 + 1];
            s5 += mind2_row(a, b4, wsh, W);
        }

        float vals[7] = {s1, s2, s3, s4, s5, s6, s7};
#pragma unroll
        for (int k = 0; k < 7; k++) {
#pragma unroll
            for (int off = 16; off > 0; off >>= 1)
                vals[k] += __shfl_down_sync(0xffffffffu, vals[k], off);
        }
        if (lane == 0) {
#pragma unroll
            for (int k = 0; k < 7; k++) lred[warp][k] = vals[k];
        }
        __syncthreads();
        if (warp == 0) {
#pragma unroll
            for (int k = 0; k < 7; k++) {
                float v = (lane < FNW) ? lred[lane][k] : 0.0f;
#pragma unroll
                for (int off = 8; off > 0; off >>= 1)
                    v += __shfl_down_sync(0xffffffffu, v, off);
                if (lane == 0) g_lpart[lb * 8 + k] = v;
            }
        }
    }

    // =================== TICKET + LOSS FINAL ===================
    __syncthreads();
    if (tid == 0) {
        __threadfence();
        unsigned t = atomicAdd(&g_cnt, 1u);
        s_last = (t == TOTAL - 1) ? 1u : 0u;
    }
    __syncthreads();
    if (s_last) {
        __threadfence();
        if (warp == 0) {
            float s[7];
#pragma unroll
            for (int k = 0; k < 7; k++) {
                float v = (lane < LB) ? g_lpart[lane * 8 + k] : 0.0f;
                if (lane + 32 < LB) v += g_lpart[(lane + 32) * 8 + k];
#pragma unroll
                for (int off = 16; off > 0; off >>= 1)
                    v += __shfl_down_sync(0xffffffffu, v, off);
                s[k] = v;   // valid on lane 0
            }
            if (lane == 0) {
                const float ws = fmaxf(ws_[0], 0.0f);
                const float S1 = s[0], S2 = s[1], S3 = s[2], S4 = s[3],
                            S5 = s[4], S6 = s[5], S7 = s[6];
                const float U_pos = -Gp * (S1 / (float)N) +
                                    ws * (S3 + S4) / (2.0f * (float)N);
                const float U_neg = -Gp * (S2 / (float)NK) +
                                    ws * ((float)KNEG * S3 + S5) / (2.0f * (float)NK);
                const float fe = fmaxf(1.0f + U_pos - U_neg, 0.0f);
                const float ke = 1e-3f * 0.5f * (S6 / (float)N) * (S7 / (float)N);
                out[N * 2] = fe + ke;
                g_cnt = 0;   // reset for next graph replay
            }
        }
    }
}

// ---------------------------------------------------------------------------
extern "C" void kernel_launch(void* const* d_in, const int* in_sizes, int n_in,
                              void* d_out, int out_size)
{
    const float* positions_2d = (const float*)d_in[0];
    const float* masses       = (const float*)d_in[1];
    const float* vel_2d       = (const float*)d_in[2];
    const float* pos_8d       = (const float*)d_in[3];
    const float* pos_pos_2d   = (const float*)d_in[4];
    const float* pos_pos_8d   = (const float*)d_in[5];
    const float* positive_m   = (const float*)d_in[6];
    const float* neg_pos_2d   = (const float*)d_in[7];
    const float* neg_pos_8d   = (const float*)d_in[8];
    const float* neg_masses   = (const float*)d_in[9];
    const float* exp_masses   = (const float*)d_in[10];
    const float* G            = (const float*)d_in[11];
    const float* rep_strength = (const float*)d_in[12];
    const float* well_centers = (const float*)d_in[13];
    const float* well_str     = (const float*)d_in[14];
    // temperature (15) / entropy_coeff (16) unused: entropy cancels.

    const int W = in_sizes[13] / 8;
    float* out = (float*)d_out;

    fused_kernel<<<TOTAL, TPB>>>(positions_2d, masses, vel_2d, pos_8d,
                                 pos_pos_2d, pos_pos_8d, positive_m,
                                 neg_pos_2d, neg_pos_8d, neg_masses,
                                 exp_masses, well_centers,
                                 G, rep_strength, well_str, W, out);
}

// round 8
// speedup vs baseline: 1.0933x; 1.0917x over previous
#include <cuda_runtime.h>
#include <cuda_bf16.h>

// Problem constants (fixed shapes from setup_inputs)
constexpr int B    = 4;
constexpr int S    = 2048;
constexpr int N    = B * S;        // 8192
constexpr int KNEG = 4;
constexpr int NK   = N * KNEG;     // 32768
constexpr int WMAX = 16;

#define SOFT 1e-6f
#define EPSF 1e-9f
#define CUT2 0.01f

constexpr int T      = 64;               // 32-row tiles per batch
constexpr int TASKS_PER_B = T * (T + 1) / 2;   // 2080
constexpr int TASKS  = TASKS_PER_B * B;  // 8320
constexpr int TPB    = 512;              // 16 warps
constexpr int FBLK   = 260;              // 260*16 = 4160 warps -> 2 tasks each
constexpr int LBL    = 36;               // loss partial blocks
constexpr int TOTAL  = FBLK + LBL;       // 296 = 2 * 148 SMs

// partial forces: [B*T global tiles][64 partner slots][32 lanes] float2 = 4 MB
__device__ __align__(16) float2 g_acc[B * T * T * 32];
__device__ __align__(16) float  g_lpart[LBL * 8];

// ---------------- raw approx MUFU ---------------------------------------
__device__ __forceinline__ float rsq(float x) {
    float r; asm("rsqrt.approx.f32 %0, %1;" : "=f"(r) : "f"(x)); return r;
}
__device__ __forceinline__ float rcp(float x) {
    float r; asm("rcp.approx.f32 %0, %1;" : "=f"(r) : "f"(x)); return r;
}

// ---------------------------------------------------------------------------
__device__ __forceinline__ float mind2_row(const float4 a, const float4 b4,
                                           const float* __restrict__ wsh, int W)
{
    float best = 3.4e38f;
    for (int w = 0; w < W; w++) {
        const float* wc = &wsh[w * 8];
        float d = 0.0f, t;
        t = a.x  - wc[0]; d = fmaf(t, t, d);
        t = a.y  - wc[1]; d = fmaf(t, t, d);
        t = a.z  - wc[2]; d = fmaf(t, t, d);
        t = a.w  - wc[3]; d = fmaf(t, t, d);
        t = b4.x - wc[4]; d = fmaf(t, t, d);
        t = b4.y - wc[5]; d = fmaf(t, t, d);
        t = b4.z - wc[6]; d = fmaf(t, t, d);
        t = b4.w - wc[7]; d = fmaf(t, t, d);
        best = fminf(best, d);
    }
    return best;   // min(dist)^2 == min(dist^2)
}

// ---------------------------------------------------------------------------
// Kernel 1. Blocks [0,FBLK): symmetric force tile-pairs, one warp per task,
// two tasks per warp (grid-stride). Blocks [FBLK,TOTAL): loss partials.
// ---------------------------------------------------------------------------
__global__ __launch_bounds__(TPB)
void force_loss_kernel(const float* __restrict__ pos,
                       const float* __restrict__ mass,
                       const float* __restrict__ vel,
                       const float* __restrict__ pos8,
                       const float* __restrict__ pp2d,
                       const float* __restrict__ pp8,
                       const float* __restrict__ pmass,
                       const float* __restrict__ np2d,
                       const float* __restrict__ np8,
                       const float* __restrict__ nmass,
                       const float* __restrict__ emass,
                       const float* __restrict__ wells,
                       const float* __restrict__ G_,
                       const float* __restrict__ rep_,
                       int W)
{
    const int tid  = threadIdx.x;
    const int lane = tid & 31;
    const int warp = tid >> 5;
    const float Gp = fmaxf(G_[0], 0.0f);

    if (blockIdx.x < FBLK) {
        // =================== SYMMETRIC FORCE ===================
        const float reps = fmaxf(rep_[0], 0.0f);
        const float c1   = -10.0f * reps;
        const float c0   = reps;
        const float2* pos2 = (const float2*)pos;
        const int wg = blockIdx.x * (TPB / 32) + warp;   // 0..4159

#pragma unroll
        for (int pass = 0; pass < 2; pass++) {
            const int t = wg + pass * 4160;              // < 8320 always
            const int b = t / TASKS_PER_B;
            const int r = t - b * TASKS_PER_B;
            // unrank r -> (I <= J): row I has (T - I) entries
            int I = (int)(64.5f - sqrtf(fmaf(-2.0f, (float)r, 4160.25f)));
            // exact integer correction (float sqrt may be 1 ulp off)
            while ((I + 1) * T - ((I + 1) * I) / 2 <= r) I++;
            while (I * T - (I * (I - 1)) / 2 > r) I--;
            const int base = I * T - (I * (I - 1)) / 2;
            const int J = I + (r - base);
            const bool diag = (I == J);

            const int ib = b * S + I * 32 + lane;
            const int jb = b * S + J * 32 + lane;
            const float2 pi = pos2[ib];
            const float  mi = mass[ib];
            const float2 pj = pos2[jb];
            float xj = pj.x, yj = pj.y, gmj = mass[jb];
            const float xi = pi.x, yi = pi.y;
            const float nGmi = -Gp * mi;

            float fix = 0.f, fiy = 0.f, fjx = 0.f, fjy = 0.f;

#pragma unroll 8
            for (int k = 0; k < 32; k++) {
                const float dx = xj - xi;
                const float dy = yj - yi;
                const float d2 = fmaf(dx, dx, fmaf(dy, dy, SOFT));
                const float u  = rsq(d2);
                const float u3 = (u * u) * u;
                float w = (nGmi * gmj) * u3;           // -(G mi mj)/d^3
                if (__any_sync(0xffffffffu, d2 < CUT2)) {
                    const float d  = d2 * u;
                    const float tt = fmaxf(fmaf(d, c1, c0), 0.0f);
                    w = fmaf(tt * rcp(fmaf(d2, d, EPSF)), u, w);
                }
                fix = fmaf(w, dx, fix);
                fiy = fmaf(w, dy, fiy);
                fjx = fmaf(-w, dx, fjx);               // Newton's 3rd law
                fjy = fmaf(-w, dy, fjy);
                // rotate j-side data + accumulators one lane
                xj  = __shfl_sync(0xffffffffu, xj,  lane + 1);
                yj  = __shfl_sync(0xffffffffu, yj,  lane + 1);
                gmj = __shfl_sync(0xffffffffu, gmj, lane + 1);
                fjx = __shfl_sync(0xffffffffu, fjx, lane + 1);
                fjy = __shfl_sync(0xffffffffu, fjy, lane + 1);
            }
            // after 32 rotations, lane L holds fj for j = J*32 + L
            const int gI = b * T + I;
            const int gJ = b * T + J;
            g_acc[(gI * T + J) * 32 + lane] = make_float2(fix, fiy);
            if (!diag)
                g_acc[(gJ * T + I) * 32 + lane] = make_float2(fjx, fjy);
        }
    } else {
        // =================== LOSS PARTIAL ===================
        __shared__ float wsh[WMAX * 8];
        __shared__ float lred[TPB / 32][8];
        const int lb = blockIdx.x - FBLK;
        if (tid < W * 8) wsh[tid] = wells[tid];
        __syncthreads();

        float s1 = 0.f, s2 = 0.f, s3 = 0.f, s4 = 0.f, s5 = 0.f, s6 = 0.f, s7 = 0.f;
        const int stride = LBL * TPB;

        for (int i = lb * TPB + tid; i < N; i += stride) {
            float2 p = ((const float2*)pos)[i];
            float2 q = ((const float2*)pp2d)[i];
            float dx = p.x - q.x, dy = p.y - q.y;
            float d2 = fmaf(dx, dx, dy * dy);
            float m = mass[i];
            s1 = fmaf(m * pmass[i], rsq(d2), s1);   // eps vs dist: <=1e-6 rel
            s6 += m;
            float2 v = ((const float2*)vel)[i];
            s7 = fmaf(v.x, v.x, fmaf(v.y, v.y, s7));

            float4 a  = ((const float4*)pos8)[i * 2];
            float4 b4 = ((const float4*)pos8)[i * 2 + 1];
            s3 += mind2_row(a, b4, wsh, W);
            a  = ((const float4*)pp8)[i * 2];
            b4 = ((const float4*)pp8)[i * 2 + 1];
            s4 += mind2_row(a, b4, wsh, W);
        }

        for (int n = lb * TPB + tid; n < NK; n += stride) {
            float2 p = ((const float2*)pos)[n / KNEG];
            float2 q = ((const float2*)np2d)[n];
            float dx = p.x - q.x, dy = p.y - q.y;
            float d2 = fmaf(dx, dx, dy * dy);
            s2 = fmaf(emass[n] * nmass[n], rsq(d2), s2);

            float4 a  = ((const float4*)np8)[n * 2];
            float4 b4 = ((const float4*)np8)[n * 2 + 1];
            s5 += mind2_row(a, b4, wsh, W);
        }

        float vals[7] = {s1, s2, s3, s4, s5, s6, s7};
#pragma unroll
        for (int k = 0; k < 7; k++) {
#pragma unroll
            for (int off = 16; off > 0; off >>= 1)
                vals[k] += __shfl_down_sync(0xffffffffu, vals[k], off);
        }
        if (lane == 0) {
#pragma unroll
            for (int k = 0; k < 7; k++) lred[warp][k] = vals[k];
        }
        __syncthreads();
        if (warp == 0) {
#pragma unroll
            for (int k = 0; k < 7; k++) {
                float v = (lane < TPB / 32) ? lred[lane][k] : 0.0f;
#pragma unroll
                for (int off = 8; off > 0; off >>= 1)
                    v += __shfl_down_sync(0xffffffffu, v, off);
                if (lane == 0) g_lpart[lb * 8 + k] = v;
            }
        }
    }
}

// ---------------------------------------------------------------------------
// Kernel 2: per-body reduce of 64 partner slots + loss final (block 0).
// grid 32 x 256 = 8192 threads, one per body.
// ---------------------------------------------------------------------------
__global__ __launch_bounds__(256)
void reduce_kernel(float* __restrict__ out,
                   const float* __restrict__ G_,
                   const float* __restrict__ ws_)
{
    const int i = blockIdx.x * 256 + threadIdx.x;   // 0..8191
    const float2* base = g_acc + (i >> 5) * (T * 32) + (i & 31);

    float fx = 0.0f, fy = 0.0f;
#pragma unroll 16
    for (int s = 0; s < T; s++) {
        const float2 v = base[s * 32];
        fx += v.x;
        fy += v.y;
    }
    ((float2*)out)[i] = make_float2(fx, fy);

    if (blockIdx.x == 0 && threadIdx.x < 32) {
        const int lane = threadIdx.x;
        float s[7];
#pragma unroll
        for (int k = 0; k < 7; k++) {
            float v = (lane < LBL) ? g_lpart[lane * 8 + k] : 0.0f;
            if (lane + 32 < LBL) v += g_lpart[(lane + 32) * 8 + k];
#pragma unroll
            for (int off = 16; off > 0; off >>= 1)
                v += __shfl_down_sync(0xffffffffu, v, off);
            s[k] = v;
        }
        if (lane == 0) {
            const float Gp = fmaxf(G_[0], 0.0f);
            const float ws = fmaxf(ws_[0], 0.0f);
            const float S1 = s[0], S2 = s[1], S3 = s[2], S4 = s[3],
                        S5 = s[4], S6 = s[5], S7 = s[6];
            const float U_pos = -Gp * (S1 / (float)N) +
                                ws * (S3 + S4) / (2.0f * (float)N);
            const float U_neg = -Gp * (S2 / (float)NK) +
                                ws * ((float)KNEG * S3 + S5) / (2.0f * (float)NK);
            // entropy term cancels in F_pos - F_neg
            const float fe = fmaxf(1.0f + U_pos - U_neg, 0.0f);
            const float ke = 1e-3f * 0.5f * (S6 / (float)N) * (S7 / (float)N);
            out[N * 2] = fe + ke;
        }
    }
}

// ---------------------------------------------------------------------------
extern "C" void kernel_launch(void* const* d_in, const int* in_sizes, int n_in,
                              void* d_out, int out_size)
{
    const float* positions_2d = (const float*)d_in[0];
    const float* masses       = (const float*)d_in[1];
    const float* vel_2d       = (const float*)d_in[2];
    const float* pos_8d       = (const float*)d_in[3];
    const float* pos_pos_2d   = (const float*)d_in[4];
    const float* pos_pos_8d   = (const float*)d_in[5];
    const float* positive_m   = (const float*)d_in[6];
    const float* neg_pos_2d   = (const float*)d_in[7];
    const float* neg_pos_8d   = (const float*)d_in[8];
    const float* neg_masses   = (const float*)d_in[9];
    const float* exp_masses   = (const float*)d_in[10];
    const float* G            = (const float*)d_in[11];
    const float* rep_strength = (const float*)d_in[12];
    const float* well_centers = (const float*)d_in[13];
    const float* well_str     = (const float*)d_in[14];
    // temperature (15) / entropy_coeff (16) unused: entropy cancels.

    const int W = in_sizes[13] / 8;
    float* out = (float*)d_out;

    force_loss_kernel<<<TOTAL, TPB>>>(positions_2d, masses, vel_2d, pos_8d,
                                      pos_pos_2d, pos_pos_8d, positive_m,
                                      neg_pos_2d, neg_pos_8d, neg_masses,
                                      exp_masses, well_centers,
                                      G, rep_strength, W);
    reduce_kernel<<<32, 256>>>(out, G, well_str);
}

// round 9
// speedup vs baseline: 1.2448x; 1.1385x over previous
#include <cuda_runtime.h>
#include <cuda_bf16.h>

// Problem constants (fixed shapes from setup_inputs)
constexpr int B    = 4;
constexpr int S    = 2048;
constexpr int N    = B * S;        // 8192
constexpr int KNEG = 4;
constexpr int NK   = N * KNEG;     // 32768
constexpr int WMAX = 16;

#define SOFT 1e-6f
#define EPSF 1e-9f
#define CUT2 0.01f

constexpr int T      = 64;               // 32-row tiles per batch
constexpr int TASKS_PER_B = T * (T + 1) / 2;   // 2080
constexpr int TPB    = 512;              // 16 warps
constexpr int FBLK   = 260;              // 260*16 = 4160 warps -> 2 tasks each
constexpr int LBL    = 36;               // loss partial blocks
constexpr int TOTAL  = FBLK + LBL;       // 296 = 2 * 148 SMs

// partial forces: [B*T global tiles][64 partner slots][32 lanes] float2 = 4 MB
__device__ __align__(16) float2 g_acc[B * T * T * 32];
__device__ __align__(16) float  g_lpart[LBL * 8];

// ---------------- raw approx MUFU ---------------------------------------
__device__ __forceinline__ float rsq(float x) {
    float r; asm("rsqrt.approx.f32 %0, %1;" : "=f"(r) : "f"(x)); return r;
}
__device__ __forceinline__ float rcp(float x) {
    float r; asm("rcp.approx.f32 %0, %1;" : "=f"(r) : "f"(x)); return r;
}

// ---------------------------------------------------------------------------
__device__ __forceinline__ float mind2_row(const float4 a, const float4 b4,
                                           const float* __restrict__ wsh, int W)
{
    float best = 3.4e38f;
    for (int w = 0; w < W; w++) {
        const float* wc = &wsh[w * 8];
        float d = 0.0f, t;
        t = a.x  - wc[0]; d = fmaf(t, t, d);
        t = a.y  - wc[1]; d = fmaf(t, t, d);
        t = a.z  - wc[2]; d = fmaf(t, t, d);
        t = a.w  - wc[3]; d = fmaf(t, t, d);
        t = b4.x - wc[4]; d = fmaf(t, t, d);
        t = b4.y - wc[5]; d = fmaf(t, t, d);
        t = b4.z - wc[6]; d = fmaf(t, t, d);
        t = b4.w - wc[7]; d = fmaf(t, t, d);
        best = fminf(best, d);
    }
    return best;   // min(dist)^2 == min(dist^2)
}

// ---------------------------------------------------------------------------
// Kernel 1. Blocks [0,FBLK): symmetric force tile-pairs, one warp per task,
// two tasks per warp. Blocks [FBLK,TOTAL): loss partials.
// ---------------------------------------------------------------------------
__global__ __launch_bounds__(TPB)
void force_loss_kernel(const float* __restrict__ pos,
                       const float* __restrict__ mass,
                       const float* __restrict__ vel,
                       const float* __restrict__ pos8,
                       const float* __restrict__ pp2d,
                       const float* __restrict__ pp8,
                       const float* __restrict__ pmass,
                       const float* __restrict__ np2d,
                       const float* __restrict__ np8,
                       const float* __restrict__ nmass,
                       const float* __restrict__ emass,
                       const float* __restrict__ wells,
                       const float* __restrict__ G_,
                       const float* __restrict__ rep_,
                       int W)
{
    const int tid  = threadIdx.x;
    const int lane = tid & 31;
    const int warp = tid >> 5;
    const float Gp = fmaxf(G_[0], 0.0f);

    if (blockIdx.x < FBLK) {
        // =================== SYMMETRIC FORCE ===================
        const float reps = fmaxf(rep_[0], 0.0f);
        const float c1   = -10.0f * reps;
        const float c0   = reps;
        const float2* pos2 = (const float2*)pos;
        const int wg = blockIdx.x * (TPB / 32) + warp;   // 0..4159

#pragma unroll
        for (int pass = 0; pass < 2; pass++) {
            const int t = wg + pass * 4160;              // < 8320 always
            const int b = t / TASKS_PER_B;
            const int r = t - b * TASKS_PER_B;
            // unrank r -> (I <= J): row I has (T - I) entries
            int I = (int)(64.5f - sqrtf(fmaf(-2.0f, (float)r, 4160.25f)));
            while ((I + 1) * T - ((I + 1) * I) / 2 <= r) I++;
            while (I * T - (I * (I - 1)) / 2 > r) I--;
            const int base = I * T - (I * (I - 1)) / 2;
            const int J = I + (r - base);
            const bool diag = (I == J);

            const int ib = b * S + I * 32 + lane;
            const int jb = b * S + J * 32 + lane;
            const float2 pi = pos2[ib];
            const float  mi = mass[ib];
            const float2 pj = pos2[jb];
            float xj = pj.x, yj = pj.y, gmj = mass[jb];
            const float xi = pi.x, yi = pi.y;
            const float nGmi = -Gp * mi;

            float fix = 0.f, fiy = 0.f, fjx = 0.f, fjy = 0.f;

#pragma unroll 8
            for (int k = 0; k < 32; k++) {
                const float dx = xj - xi;
                const float dy = yj - yi;
                const float d2 = fmaf(dx, dx, fmaf(dy, dy, SOFT));
                const float u  = rsq(d2);
                const float u3 = (u * u) * u;
                float w = (nGmi * gmj) * u3;           // -(G mi mj)/d^3
                if (__any_sync(0xffffffffu, d2 < CUT2)) {
                    const float d  = d2 * u;
                    const float tt = fmaxf(fmaf(d, c1, c0), 0.0f);
                    w = fmaf(tt * rcp(fmaf(d2, d, EPSF)), u, w);
                }
                fix = fmaf(w, dx, fix);
                fiy = fmaf(w, dy, fiy);
                fjx = fmaf(-w, dx, fjx);               // Newton's 3rd law
                fjy = fmaf(-w, dy, fjy);
                // rotate j-side data + accumulators one lane
                xj  = __shfl_sync(0xffffffffu, xj,  lane + 1);
                yj  = __shfl_sync(0xffffffffu, yj,  lane + 1);
                gmj = __shfl_sync(0xffffffffu, gmj, lane + 1);
                fjx = __shfl_sync(0xffffffffu, fjx, lane + 1);
                fjy = __shfl_sync(0xffffffffu, fjy, lane + 1);
            }
            // after 32 rotations, lane L holds fj for j = J*32 + L
            const int gI = b * T + I;
            const int gJ = b * T + J;
            g_acc[(gI * T + J) * 32 + lane] = make_float2(fix, fiy);
            if (!diag)
                g_acc[(gJ * T + I) * 32 + lane] = make_float2(fjx, fjy);
        }
    } else {
        // =================== LOSS PARTIAL ===================
        __shared__ float wsh[WMAX * 8];
        __shared__ float lred[TPB / 32][8];
        const int lb = blockIdx.x - FBLK;
        if (tid < W * 8) wsh[tid] = wells[tid];
        __syncthreads();

        float s1 = 0.f, s2 = 0.f, s3 = 0.f, s4 = 0.f, s5 = 0.f, s6 = 0.f, s7 = 0.f;
        const int stride = LBL * TPB;

        for (int i = lb * TPB + tid; i < N; i += stride) {
            float2 p = ((const float2*)pos)[i];
            float2 q = ((const float2*)pp2d)[i];
            float dx = p.x - q.x, dy = p.y - q.y;
            float d2 = fmaf(dx, dx, dy * dy);
            float m = mass[i];
            s1 = fmaf(m * pmass[i], rsq(d2), s1);   // eps vs dist: <=1e-6 rel
            s6 += m;
            float2 v = ((const float2*)vel)[i];
            s7 = fmaf(v.x, v.x, fmaf(v.y, v.y, s7));

            float4 a  = ((const float4*)pos8)[i * 2];
            float4 b4 = ((const float4*)pos8)[i * 2 + 1];
            s3 += mind2_row(a, b4, wsh, W);
            a  = ((const float4*)pp8)[i * 2];
            b4 = ((const float4*)pp8)[i * 2 + 1];
            s4 += mind2_row(a, b4, wsh, W);
        }

        for (int n = lb * TPB + tid; n < NK; n += stride) {
            float2 p = ((const float2*)pos)[n / KNEG];
            float2 q = ((const float2*)np2d)[n];
            float dx = p.x - q.x, dy = p.y - q.y;
            float d2 = fmaf(dx, dx, dy * dy);
            s2 = fmaf(emass[n] * nmass[n], rsq(d2), s2);

            float4 a  = ((const float4*)np8)[n * 2];
            float4 b4 = ((const float4*)np8)[n * 2 + 1];
            s5 += mind2_row(a, b4, wsh, W);
        }

        float vals[7] = {s1, s2, s3, s4, s5, s6, s7};
#pragma unroll
        for (int k = 0; k < 7; k++) {
#pragma unroll
            for (int off = 16; off > 0; off >>= 1)
                vals[k] += __shfl_down_sync(0xffffffffu, vals[k], off);
        }
        if (lane == 0) {
#pragma unroll
            for (int k = 0; k < 7; k++) lred[warp][k] = vals[k];
        }
        __syncthreads();
        if (warp == 0) {
#pragma unroll
            for (int k = 0; k < 7; k++) {
                float v = (lane < TPB / 32) ? lred[lane][k] : 0.0f;
#pragma unroll
                for (int off = 8; off > 0; off >>= 1)
                    v += __shfl_down_sync(0xffffffffu, v, off);
                if (lane == 0) g_lpart[lb * 8 + k] = v;
            }
        }
    }
}

// ---------------------------------------------------------------------------
// Kernel 2: per-body reduce of 64 partner slots + loss final (block 0).
// grid 256 x 32: one block per tile, one lane per body. 256 CTAs spread over
// all SMs; 64 independent 256B-coalesced loads per warp hide L2 latency.
// ---------------------------------------------------------------------------
__global__ __launch_bounds__(32)
void reduce_kernel(float* __restrict__ out,
                   const float* __restrict__ G_,
                   const float* __restrict__ ws_)
{
    const int tile = blockIdx.x;                 // 0..255
    const int lane = threadIdx.x;                // 0..31
    const float2* base = g_acc + tile * (T * 32) + lane;

    float fx = 0.0f, fy = 0.0f;
#pragma unroll
    for (int s = 0; s < T; s++) {
        const float2 v = base[s * 32];
        fx += v.x;
        fy += v.y;
    }
    ((float2*)out)[tile * 32 + lane] = make_float2(fx, fy);

    if (blockIdx.x == 0) {
        float s[7];
#pragma unroll
        for (int k = 0; k < 7; k++) {
            float v = (lane < LBL) ? g_lpart[lane * 8 + k] : 0.0f;
            if (lane + 32 < LBL) v += g_lpart[(lane + 32) * 8 + k];
#pragma unroll
            for (int off = 16; off > 0; off >>= 1)
                v += __shfl_down_sync(0xffffffffu, v, off);
            s[k] = v;
        }
        if (lane == 0) {
            const float Gp = fmaxf(G_[0], 0.0f);
            const float ws = fmaxf(ws_[0], 0.0f);
            const float S1 = s[0], S2 = s[1], S3 = s[2], S4 = s[3],
                        S5 = s[4], S6 = s[5], S7 = s[6];
            const float U_pos = -Gp * (S1 / (float)N) +
                                ws * (S3 + S4) / (2.0f * (float)N);
            const float U_neg = -Gp * (S2 / (float)NK) +
                                ws * ((float)KNEG * S3 + S5) / (2.0f * (float)NK);
            // entropy term cancels in F_pos - F_neg
            const float fe = fmaxf(1.0f + U_pos - U_neg, 0.0f);
            const float ke = 1e-3f * 0.5f * (S6 / (float)N) * (S7 / (float)N);
            out[N * 2] = fe + ke;
        }
    }
}

// ---------------------------------------------------------------------------
extern "C" void kernel_launch(void* const* d_in, const int* in_sizes, int n_in,
                              void* d_out, int out_size)
{
    const float* positions_2d = (const float*)d_in[0];
    const float* masses       = (const float*)d_in[1];
    const float* vel_2d       = (const float*)d_in[2];
    const float* pos_8d       = (const float*)d_in[3];
    const float* pos_pos_2d   = (const float*)d_in[4];
    const float* pos_pos_8d   = (const float*)d_in[5];
    const float* positive_m   = (const float*)d_in[6];
    const float* neg_pos_2d   = (const float*)d_in[7];
    const float* neg_pos_8d   = (const float*)d_in[8];
    const float* neg_masses   = (const float*)d_in[9];
    const float* exp_masses   = (const float*)d_in[10];
    const float* G            = (const float*)d_in[11];
    const float* rep_strength = (const float*)d_in[12];
    const float* well_centers = (const float*)d_in[13];
    const float* well_str     = (const float*)d_in[14];
    // temperature (15) / entropy_coeff (16) unused: entropy cancels.

    const int W = in_sizes[13] / 8;
    float* out = (float*)d_out;

    force_loss_kernel<<<TOTAL, TPB>>>(positions_2d, masses, vel_2d, pos_8d,
                                      pos_pos_2d, pos_pos_8d, positive_m,
                                      neg_pos_2d, neg_pos_8d, neg_masses,
                                      exp_masses, well_centers,
                                      G, rep_strength, W);
    reduce_kernel<<<256, 32>>>(out, G, well_str);
}